// round 3
// baseline (speedup 1.0000x reference)
#include <cuda_runtime.h>
#include <cuda_bf16.h>

// B=262144, G=25, KIN=15, KOUT=3
// x: (B,375) f32 ; W: (25,3,15) f32 ; k_idx: (25,15) i32 ; v_idx: (25,3) i32
// out: (B,75) f32
//
// cp.async double-buffered streaming kernel. One thread per output element
// p=g*3+o (75) x 4 row slots = 300 threads. W[g,o,:], k_idx[g,:], v_idx[p]
// live in registers for the whole (persistent) block. Tile t+1 is prefetched
// with cp.async.cg into the alternate buffer while tile t is computed.

static constexpr int G     = 25;
static constexpr int KIN   = 15;
static constexpr int KOUT  = 3;
static constexpr int ROW_F = G * KIN;        // 375
static constexpr int OUT_F = G * KOUT;       // 75
static constexpr int ROWS  = 16;             // rows per tile
static constexpr int SLOTS = 4;
static constexpr int NT    = OUT_F * SLOTS;  // 300 threads
static constexpr int RPT   = ROWS / SLOTS;   // 4 rows per thread
static constexpr int XF_TILE = ROWS * ROW_F;         // 6000 floats
static constexpr int X4_TILE = XF_TILE / 4;          // 1500 float4
static constexpr int X4_THR  = X4_TILE / NT;         // 5 per thread
static constexpr size_t SMEM_BYTES =
    (size_t)(2 * XF_TILE + ROWS * OUT_F) * sizeof(float);  // 52800

__device__ __forceinline__ void cp16(float* sdst, const float4* gsrc) {
    unsigned s = (unsigned)__cvta_generic_to_shared(sdst);
    asm volatile("cp.async.cg.shared.global [%0], [%1], 16;" :: "r"(s), "l"(gsrc));
}

__global__ void __launch_bounds__(NT, 4)
mlp_rsna4_kernel(const float* __restrict__ x,
                 const float* __restrict__ W,
                 const int*   __restrict__ kidx,
                 const int*   __restrict__ vidx,
                 float*       __restrict__ out,
                 int B, int ntiles)
{
    extern __shared__ float smem[];
    float* sxbuf[2] = { smem, smem + XF_TILE };
    float* sout     = smem + 2 * XF_TILE;          // ROWS*OUT_F floats
    float4* so4     = reinterpret_cast<float4*>(sout);

    const int tid  = threadIdx.x;
    const int p    = tid % OUT_F;   // 0..74
    const int slot = tid / OUT_F;   // 0..3
    const int g    = p / KOUT;
    const int o    = p % KOUT;

    float w[KIN];
    int   kid[KIN];
    #pragma unroll
    for (int i = 0; i < KIN; i++) {
        w[i]   = __ldg(&W[(g * KOUT + o) * KIN + i]);
        kid[i] = __ldg(&kidx[g * KIN + i]);
    }
    const int vo = __ldg(&vidx[p]);

    // ---- async stage of one tile into buffer b ----
    auto stage = [&](int tile, int b) {
        const long long row0 = (long long)tile * ROWS;
        const float4* gx4 = reinterpret_cast<const float4*>(x + row0 * ROW_F);
        float* sb = sxbuf[b];
        if (row0 + ROWS <= (long long)B) {
            #pragma unroll
            for (int k = 0; k < X4_THR; k++) {
                int j = tid + k * NT;
                cp16(sb + 4 * j, gx4 + j);
            }
        } else {
            const long long lim4 = ((long long)B - row0) * ROW_F / 4;
            #pragma unroll
            for (int k = 0; k < X4_THR; k++) {
                int j = tid + k * NT;
                if (j < lim4) cp16(sb + 4 * j, gx4 + j);
                else reinterpret_cast<float4*>(sb)[j] = make_float4(0.f,0.f,0.f,0.f);
            }
        }
    };

    int tile = blockIdx.x;
    if (tile < ntiles) stage(tile, 0);
    asm volatile("cp.async.commit_group;");

    int buf = 0;
    for (; tile < ntiles; tile += gridDim.x) {
        const int nxt = tile + gridDim.x;
        if (nxt < ntiles) stage(nxt, buf ^ 1);
        asm volatile("cp.async.commit_group;");

        so4[tid] = make_float4(0.f, 0.f, 0.f, 0.f);   // own element only: no hazard

        asm volatile("cp.async.wait_group 1;");
        __syncthreads();                               // sx[buf] ready for all

        // ---- compute 4 rows (ILP) ----
        const float* sb = sxbuf[buf] + slot * ROW_F;
        float acc[RPT];
        #pragma unroll
        for (int rr = 0; rr < RPT; rr++) acc[rr] = 0.f;
        #pragma unroll
        for (int i = 0; i < KIN; i++) {
            const int   c  = kid[i];
            const float wi = w[i];
            #pragma unroll
            for (int rr = 0; rr < RPT; rr++)
                acc[rr] = fmaf(sb[rr * (SLOTS * ROW_F) + c], wi, acc[rr]);
        }
        #pragma unroll
        for (int rr = 0; rr < RPT; rr++)
            sout[(rr * SLOTS + slot) * OUT_F + vo] = acc[rr];
        __syncthreads();

        // ---- coalesced float4 store of out tile ----
        const long long row0 = (long long)tile * ROWS;
        float4* go4 = reinterpret_cast<float4*>(out + row0 * OUT_F);
        if (row0 + ROWS <= (long long)B) {
            go4[tid] = so4[tid];
        } else {
            const long long lim4 = ((long long)B - row0) * OUT_F / 4;
            if (tid < lim4) go4[tid] = so4[tid];
        }
        buf ^= 1;
    }
}

extern "C" void kernel_launch(void* const* d_in, const int* in_sizes, int n_in,
                              void* d_out, int out_size)
{
    const float* x    = (const float*)d_in[0];
    const float* W    = (const float*)d_in[1];
    const int*   kidx = (const int*)d_in[2];
    const int*   vidx = (const int*)d_in[3];
    float*       out  = (float*)d_out;

    const int B = in_sizes[0] / ROW_F;
    const int ntiles = (B + ROWS - 1) / ROWS;

    cudaFuncSetAttribute(mlp_rsna4_kernel,
                         cudaFuncAttributeMaxDynamicSharedMemorySize,
                         (int)SMEM_BYTES);

    int grid = 148 * 4;                 // persistent: 4 blocks/SM
    if (grid > ntiles) grid = ntiles;

    mlp_rsna4_kernel<<<grid, NT, SMEM_BYTES>>>(x, W, kidx, vidx, out, B, ntiles);
}

// round 4
// speedup vs baseline: 1.1135x; 1.1135x over previous
#include <cuda_runtime.h>
#include <cuda_bf16.h>

// B=262144, G=25, KIN=15, KOUT=3
// x: (B,375) f32 ; W: (25,3,15) f32 ; k_idx: (25,15) i32 ; v_idx: (25,3) i32
// out: (B,75) f32
//
// Persistent, double-buffered streaming kernel. One thread per output element
// p=g*3+o (75) x 4 row slots = 300 threads. W[g,o,:], k_idx[g,:], v_idx[p] in
// registers for the whole block. Each iteration: issue LDG for tile t+1 into
// buf^1 (front-batched, overlaps compute), compute tile t from buf, store out
// DIRECTLY to global (coalesced STG.32 per warp), single __syncthreads.

static constexpr int G     = 25;
static constexpr int KIN   = 15;
static constexpr int KOUT  = 3;
static constexpr int ROW_F = G * KIN;        // 375
static constexpr int OUT_F = G * KOUT;       // 75
static constexpr int ROWS  = 16;             // rows per tile
static constexpr int SLOTS = 4;
static constexpr int NT    = OUT_F * SLOTS;  // 300 threads
static constexpr int RPT   = ROWS / SLOTS;   // 4 rows per thread
static constexpr int XF_TILE = ROWS * ROW_F;         // 6000 floats
static constexpr int X4_TILE = XF_TILE / 4;          // 1500 float4
static constexpr int X4_THR  = X4_TILE / NT;         // 5 per thread
static constexpr size_t SMEM_BYTES = (size_t)(2 * XF_TILE) * sizeof(float); // 48000

__global__ void __launch_bounds__(NT, 4)
mlp_rsna4_kernel(const float* __restrict__ x,
                 const float* __restrict__ W,
                 const int*   __restrict__ kidx,
                 const int*   __restrict__ vidx,
                 float*       __restrict__ out,
                 int B, int ntiles)
{
    extern __shared__ float smem[];
    float* sxbuf[2] = { smem, smem + XF_TILE };

    const int tid  = threadIdx.x;
    const int p    = tid % OUT_F;   // 0..74
    const int slot = tid / OUT_F;   // 0..3
    const int g    = p / KOUT;
    const int o    = p % KOUT;

    float w[KIN];
    int   kid[KIN];
    #pragma unroll
    for (int i = 0; i < KIN; i++) {
        w[i]   = __ldg(&W[(g * KOUT + o) * KIN + i]);
        kid[i] = __ldg(&kidx[g * KIN + i]);
    }
    const int vo = __ldg(&vidx[p]);

    // Stage one tile into buffer b: plain LDG.128 -> STS.128 (LDGs front-batch)
    auto stage = [&](int tile, int b) {
        const long long row0 = (long long)tile * ROWS;
        const float4* gx4 = reinterpret_cast<const float4*>(x + row0 * ROW_F);
        float4* sb4 = reinterpret_cast<float4*>(sxbuf[b]);
        if (row0 + ROWS <= (long long)B) {
            float4 v[X4_THR];
            #pragma unroll
            for (int k = 0; k < X4_THR; k++) v[k] = gx4[tid + k * NT];
            #pragma unroll
            for (int k = 0; k < X4_THR; k++) sb4[tid + k * NT] = v[k];
        } else {
            const long long lim4 = ((long long)B - row0) * ROW_F / 4;
            #pragma unroll
            for (int k = 0; k < X4_THR; k++) {
                int j = tid + k * NT;
                sb4[j] = (j < lim4) ? gx4[j] : make_float4(0.f, 0.f, 0.f, 0.f);
            }
        }
    };

    int tile = blockIdx.x;
    if (tile < ntiles) stage(tile, 0);
    __syncthreads();

    int buf = 0;
    for (; tile < ntiles; tile += gridDim.x) {
        // Prefetch next tile into the other buffer; its LDGs overlap the
        // compute below (no dependency), STS retire before the barrier.
        const int nxt = tile + gridDim.x;
        if (nxt < ntiles) stage(nxt, buf ^ 1);

        // ---- compute RPT rows (independent acc chains) ----
        const float* sb = sxbuf[buf] + slot * ROW_F;
        float acc[RPT];
        #pragma unroll
        for (int rr = 0; rr < RPT; rr++) acc[rr] = 0.f;
        #pragma unroll
        for (int i = 0; i < KIN; i++) {
            const int   c  = kid[i];
            const float wi = w[i];
            #pragma unroll
            for (int rr = 0; rr < RPT; rr++)
                acc[rr] = fmaf(sb[rr * (SLOTS * ROW_F) + c], wi, acc[rr]);
        }

        // ---- direct scatter-store: lanes cover consecutive out columns ----
        const long long row0 = (long long)tile * ROWS;
        #pragma unroll
        for (int rr = 0; rr < RPT; rr++) {
            const long long r = row0 + rr * SLOTS + slot;
            if (r < (long long)B) out[r * OUT_F + vo] = acc[rr];
        }

        __syncthreads();   // buf^1 staged for all; buf free to be overwritten
        buf ^= 1;
    }
}

extern "C" void kernel_launch(void* const* d_in, const int* in_sizes, int n_in,
                              void* d_out, int out_size)
{
    const float* x    = (const float*)d_in[0];
    const float* W    = (const float*)d_in[1];
    const int*   kidx = (const int*)d_in[2];
    const int*   vidx = (const int*)d_in[3];
    float*       out  = (float*)d_out;

    const int B = in_sizes[0] / ROW_F;
    const int ntiles = (B + ROWS - 1) / ROWS;

    cudaFuncSetAttribute(mlp_rsna4_kernel,
                         cudaFuncAttributeMaxDynamicSharedMemorySize,
                         (int)SMEM_BYTES);

    int grid = 148 * 4;                 // persistent: 4 blocks/SM
    if (grid > ntiles) grid = ntiles;

    mlp_rsna4_kernel<<<grid, NT, SMEM_BYTES>>>(x, W, kidx, vidx, out, B, ntiles);
}